// round 6
// baseline (speedup 1.0000x reference)
#include <cuda_runtime.h>
#include <cstdint>

#define BB 256
#define LL 1024
#define TT 128
#define GRID 152

// ---------------------------------------------------------------------------
// One fused kernel. Per CTA:
//   - sniff index dtype (int32 vs int64) from sequence_lengths layout
//   - build LPT schedule locally (rank by counting; no globals, no atomics)
//   - for each assigned batch: sequence score (gather) + forward recursion
// Thread t owns alpha[t]; exp(trans[.][t]) column lives in 128 registers.
// Per step: offset-stabilized exp, one barrier, 128-FMA dot, one log.
// ---------------------------------------------------------------------------
__global__ void __launch_bounds__(128)
crf_all(const float* __restrict__ inputs,
        const int*   __restrict__ tags32,     // int32 words of tag_indices
        const int*   __restrict__ slen32,     // int32 words of sequence_lengths
        const float* __restrict__ trans,
        float* __restrict__ out)
{
    const int t = threadIdx.x;

    // ---- dtype sniff: int64 layout => odd words of seqlen are high words (0).
    //      int32 layout => odd words are real lengths (>=1). Deterministic. ----
    const int stride = ((slen32[1] | slen32[3] | slen32[5] | slen32[7]) == 0) ? 2 : 1;

    __shared__ int slen[BB];
    __shared__ int inv[BB];                       // inv[rank] = batch id
    __shared__ __align__(16) float sh_ea[2][TT];  // exp(alpha - off), dbl buf
    __shared__ float sh_off[2];
    __shared__ float sh_red[TT];                  // reduction scratch

    // ---- lengths (clamped so no data can produce wild addresses) ----
    for (int i = t; i < BB; i += 128) {
        int v = slen32[(size_t)i * stride];
        if (v < 1) v = 1; if (v > LL) v = LL;
        slen[i] = v;
    }
    __syncthreads();

    // ---- local LPT schedule: rank batches by descending step count ----
    for (int i = t; i < BB; i += 128) {
        unsigned key_i = ((unsigned)(slen[i]) << 8) | (unsigned)i;
        int r = 0;
        for (int j = 0; j < BB; j++) {
            unsigned key_j = ((unsigned)(slen[j]) << 8) | (unsigned)j;
            r += (key_j > key_i) ? 1 : 0;         // descending rank
        }
        inv[r] = i;                               // keys unique (id in low bits)
    }

    // ---- exp(trans) column for this thread's output tag (registers) ----
    float eT[TT];
    #pragma unroll
    for (int s = 0; s < TT; s++) eT[s] = __expf(trans[s * TT + t]);
    __syncthreads();                              // inv[] ready

    // static schedule: CTA i -> rank i; CTAs 0..(BB-1-GRID) also -> rank 255-i
    const int nb = ((int)blockIdx.x <= BB - 1 - GRID) ? 2 : 1;

    for (int q = 0; q < nb; q++) {
        int rank = (q == 0) ? (int)blockIdx.x : (BB - 1 - (int)blockIdx.x);
        int b = inv[rank];
        int len = slen[b];
        int nsteps = len - 1; if (nsteps < 1) nsteps = 1;
        const float* inp = inputs + (size_t)b * LL * TT;
        const int*   tg  = tags32 + (size_t)b * LL * stride;

        // ---- sequence score: unary + transition gathers, masked ----
        float s = 0.f;
        for (int l = t; l < len; l += 128) {
            int cur = tg[(size_t)l * stride] & (TT - 1);
            s += inp[(size_t)l * TT + cur];
            if (l > 0) {
                int prev = tg[(size_t)(l - 1) * stride] & (TT - 1);
                s += trans[prev * TT + cur];
            }
        }
        sh_red[t] = s;
        __syncthreads();
        for (int o = 64; o > 0; o >>= 1) {
            if (t < o) sh_red[t] += sh_red[t + o];
            __syncthreads();
        }
        float seqscore = sh_red[0];
        __syncthreads();                          // WAR guard on sh_red

        // ---- forward recursion ----
        float alpha = inp[t];
        if (t == 0) sh_off[1] = alpha;            // slot 1: not touched by iter 1
        __syncthreads();
        float Mprev = sh_off[1];                  // offset (thread 0's alpha)
        float inp_next = inp[TT + t];             // row 1 always exists (L=1024)
        int buf = 0;

        for (int l = 1; l <= nsteps; l++) {
            float ea = __expf(alpha - Mprev);
            sh_ea[buf][t] = ea;
            if (t == 0) sh_off[buf] = alpha;      // next step's offset
            float inp_cur = inp_next;
            __syncthreads();
            float Mnext = sh_off[buf];
            if (l < nsteps) inp_next = inp[(size_t)(l + 1) * TT + t];

            const float4* ev = reinterpret_cast<const float4*>(sh_ea[buf]);
            float a0 = 0.f, a1 = 0.f, a2 = 0.f, a3 = 0.f;
            #pragma unroll
            for (int k = 0; k < TT / 4; k++) {
                float4 e = ev[k];
                a0 = fmaf(e.x, eT[4 * k + 0], a0);
                a1 = fmaf(e.y, eT[4 * k + 1], a1);
                a2 = fmaf(e.z, eT[4 * k + 2], a2);
                a3 = fmaf(e.w, eT[4 * k + 3], a3);
            }
            float acc = (a0 + a2) + (a1 + a3);
            alpha = inp_cur + Mprev + __logf(acc);
            Mprev = Mnext;
            buf ^= 1;
        }

        // ---- final logsumexp over alpha (shared-mem trees) ----
        sh_red[t] = alpha;
        __syncthreads();
        for (int o = 64; o > 0; o >>= 1) {
            if (t < o) sh_red[t] = fmaxf(sh_red[t], sh_red[t + o]);
            __syncthreads();
        }
        float fm = sh_red[0];
        __syncthreads();                          // WAR guard
        sh_red[t] = __expf(alpha - fm);
        __syncthreads();
        for (int o = 64; o > 0; o >>= 1) {
            if (t < o) sh_red[t] += sh_red[t + o];
            __syncthreads();
        }
        if (t == 0) out[b] = seqscore - (fm + __logf(sh_red[0]));
        __syncthreads();                          // protect shared before next batch
    }
}

// ---------------------------------------------------------------------------
extern "C" void kernel_launch(void* const* d_in, const int* in_sizes, int n_in,
                              void* d_out, int out_size) {
    const float* inputs = (const float*)d_in[0];
    const int*   tags32 = (const int*)d_in[1];
    const int*   slen32 = (const int*)d_in[2];
    const float* trans  = (const float*)d_in[3];
    float* outp = (float*)d_out;

    crf_all<<<GRID, 128>>>(inputs, tags32, slen32, trans, outp);
}